// round 4
// baseline (speedup 1.0000x reference)
#include <cuda_runtime.h>
#include <math.h>

// Problem dimensions (fixed by the reference setup_inputs)
#define TOK     2048   // B*S = 2*1024
#define D_MODEL  512
#define N_IN    2048
#define N_PROC  1024
#define D_PV     256
#define N_OUT   2048
#define K_IN     256
#define K_PROC   128
#define K_OUT    256

typedef unsigned long long u64;

// Scratch (no cudaMalloc allowed): 16 + 8 + 2 + 16 = 42 MB
__device__ float g_acts1[TOK * N_IN];     // stage1 gelu acts (16 MB)
__device__ float g_pwt  [N_IN * N_PROC];  // process_input_weights^T (8 MB)
__device__ float g_agg  [TOK * D_PV];     // softmax-weighted value aggregate (2 MB)
__device__ float g_acts3[TOK * N_OUT];    // stage3 gelu acts (16 MB)

// ---------------------------------------------------------------------------
// helpers
// ---------------------------------------------------------------------------
__device__ __forceinline__ float gelu_exact(float x) {
    // jax approximate=False: 0.5*x*(1+erf(x/sqrt(2)))
    return 0.5f * x * (1.0f + erff(x * 0.70710678118654752f));
}

// packed 2xfp32 FMA (sm_100+; ptxas never emits this from C++)
__device__ __forceinline__ void ffma2(u64& d, u64 a, u64 b) {
    asm("fma.rn.f32x2 %0, %1, %2, %0;" : "+l"(d) : "l"(a), "l"(b));
}
__device__ __forceinline__ u64 pack_dup(float v) {
    u64 r; asm("mov.b64 %0, {%1, %1};" : "=l"(r) : "f"(v)); return r;
}
__device__ __forceinline__ void unpack2(u64 v, float& lo, float& hi) {
    asm("mov.b64 {%0, %1}, %2;" : "=f"(lo), "=f"(hi) : "l"(v));
}

// monotonic float -> uint mapping (no NaNs in this workload)
__device__ __forceinline__ unsigned f2key(float f) {
    unsigned u = __float_as_uint(f);
    return (u & 0x80000000u) ? ~u : (u | 0x80000000u);
}

// Exact k-th largest key across the block via MSB radix select.
// Each thread holds EPT keys in registers. s_cnts: 32 ints (zeroed inside).
// All threads of the block must participate.
template<int EPT>
__device__ unsigned radix_select_kth(const unsigned (&keys)[EPT], int k, int* s_cnts) {
    if (threadIdx.x < 32) s_cnts[threadIdx.x] = 0;
    __syncthreads();
    unsigned prefix = 0;
    int kk = k;
    #pragma unroll 1
    for (int b = 31; b >= 0; b--) {
        const unsigned mask = ~((1u << b) - 1u);   // bits [31..b]
        const unsigned cand = prefix | (1u << b);
        int local = 0;
        #pragma unroll
        for (int j = 0; j < EPT; j++)
            local += ((keys[j] & mask) == cand) ? 1 : 0;
        #pragma unroll
        for (int o = 16; o > 0; o >>= 1)
            local += __shfl_xor_sync(0xffffffffu, local, o);
        if ((threadIdx.x & 31) == 0) atomicAdd(&s_cnts[b], local);
        __syncthreads();
        const int cnt = s_cnts[b];
        if (cnt >= kk) prefix = cand;
        else           kk -= cnt;
        // next iteration uses a different counter slot -> no extra barrier
    }
    return prefix;  // key of k-th largest; selected set = (key >= prefix)
}

__device__ __forceinline__ float block_max(float v, float* sh) {
    #pragma unroll
    for (int o = 16; o > 0; o >>= 1) v = fmaxf(v, __shfl_xor_sync(0xffffffffu, v, o));
    if ((threadIdx.x & 31) == 0) sh[threadIdx.x >> 5] = v;
    __syncthreads();
    if (threadIdx.x == 0) {
        const int nw = blockDim.x >> 5;
        float r = sh[0];
        for (int i = 1; i < nw; i++) r = fmaxf(r, sh[i]);
        sh[0] = r;
    }
    __syncthreads();
    float r = sh[0];
    __syncthreads();
    return r;
}

__device__ __forceinline__ float block_sum(float v, float* sh) {
    #pragma unroll
    for (int o = 16; o > 0; o >>= 1) v += __shfl_xor_sync(0xffffffffu, v, o);
    if ((threadIdx.x & 31) == 0) sh[threadIdx.x >> 5] = v;
    __syncthreads();
    if (threadIdx.x == 0) {
        const int nw = blockDim.x >> 5;
        float r = sh[0];
        for (int i = 1; i < nw; i++) r += sh[i];
        sh[0] = r;
    }
    __syncthreads();
    float r = sh[0];
    __syncthreads();
    return r;
}

// ---------------------------------------------------------------------------
// Tiled fp32 GEMM: C[M,N] = gelu(A[M,K] * B[N,K]^T)
// 128x128 tile, BK=8, 256 threads, 8x8 microtile, double-buffered smem,
// fma.rn.f32x2 packed inner product (bit-identical to scalar FFMA).
// Requires M,N % 128 == 0, K % 8 == 0 (true for all call sites).
// ---------------------------------------------------------------------------
__device__ __forceinline__ void gemm_abt_gelu_body(
        const float* __restrict__ A, const float* __restrict__ B,
        float* __restrict__ C, int N, int K) {
    __shared__ __align__(16) float As[2][8][128];
    __shared__ __align__(16) float Bs[2][8][128];

    const int tid = threadIdx.x;
    const int tx = tid & 15;         // 0..15 -> col group (8 cols each)
    const int ty = tid >> 4;         // 0..15 -> row group (8 rows each)
    const int bm = blockIdx.y * 128;
    const int bn = blockIdx.x * 128;

    const int lr = tid >> 1;         // 0..127 row within tile (load)
    const int lc = (tid & 1) << 2;   // 0 or 4 within BK (load)

    const float* Ap = A + (size_t)(bm + lr) * K + lc;
    const float* Bp = B + (size_t)(bn + lr) * K + lc;

    u64 acc2[8][4] = {};             // acc2[i][j2] = cols (2*j2, 2*j2+1) packed

    float4 a4 = *(const float4*)(Ap);
    float4 b4 = *(const float4*)(Bp);
    int buf = 0;

    for (int k0 = 0; k0 < K; k0 += 8) {
        As[buf][lc + 0][lr] = a4.x; As[buf][lc + 1][lr] = a4.y;
        As[buf][lc + 2][lr] = a4.z; As[buf][lc + 3][lr] = a4.w;
        Bs[buf][lc + 0][lr] = b4.x; Bs[buf][lc + 1][lr] = b4.y;
        Bs[buf][lc + 2][lr] = b4.z; Bs[buf][lc + 3][lr] = b4.w;
        __syncthreads();
        if (k0 + 8 < K) {                       // prefetch next k-slab
            a4 = *(const float4*)(Ap + k0 + 8);
            b4 = *(const float4*)(Bp + k0 + 8);
        }
        #pragma unroll
        for (int kk = 0; kk < 8; kk++) {
            float av[8];
            *(float4*)&av[0] = *(const float4*)&As[buf][kk][ty * 8 + 0];
            *(float4*)&av[4] = *(const float4*)&As[buf][kk][ty * 8 + 4];
            // contiguous smem fp32 pairs ARE the packed f32x2 operand
            const u64* bq = (const u64*)&Bs[buf][kk][tx * 8];
            const u64 b0 = bq[0], b1 = bq[1], b2 = bq[2], b3 = bq[3];
            #pragma unroll
            for (int i = 0; i < 8; i++) {
                const u64 ad = pack_dup(av[i]);
                ffma2(acc2[i][0], ad, b0);
                ffma2(acc2[i][1], ad, b1);
                ffma2(acc2[i][2], ad, b2);
                ffma2(acc2[i][3], ad, b3);
            }
        }
        buf ^= 1;   // safe: next write targets the other buffer; re-use of this
                    // one is fenced by the barrier in the next iteration
    }

    #pragma unroll
    for (int i = 0; i < 8; i++) {
        const int m = bm + ty * 8 + i;
        float r[8];
        #pragma unroll
        for (int j2 = 0; j2 < 4; j2++) {
            float lo, hi;
            unpack2(acc2[i][j2], lo, hi);
            r[2 * j2 + 0] = gelu_exact(lo);
            r[2 * j2 + 1] = gelu_exact(hi);
        }
        float* cp = C + (size_t)m * N + bn + tx * 8;
        *(float4*)(cp + 0) = *(const float4*)&r[0];
        *(float4*)(cp + 4) = *(const float4*)&r[4];
    }
}

__global__ __launch_bounds__(256) void k_gemm1(const float* __restrict__ x,
                                               const float* __restrict__ IP) {
    gemm_abt_gelu_body(x, IP, g_acts1, N_IN, D_MODEL);
}
__global__ __launch_bounds__(256) void k_gemm3(const float* __restrict__ OW) {
    gemm_abt_gelu_body(g_agg, OW, g_acts3, N_OUT, D_PV);
}

// ---------------------------------------------------------------------------
// Transpose PW [N_PROC, N_IN] -> g_pwt [N_IN, N_PROC]
// ---------------------------------------------------------------------------
__global__ __launch_bounds__(256) void k_transpose(const float* __restrict__ PW) {
    __shared__ float tile[32][33];
    const int n0 = blockIdx.x * 32;
    const int p0 = blockIdx.y * 32;
    const int tx = threadIdx.x & 31;
    const int ty8 = threadIdx.x >> 5;       // 0..7
    #pragma unroll
    for (int i = 0; i < 4; i++) {
        const int p = ty8 + i * 8;
        tile[p][tx] = PW[(size_t)(p0 + p) * N_IN + n0 + tx];
    }
    __syncthreads();
    #pragma unroll
    for (int i = 0; i < 4; i++) {
        const int n = ty8 + i * 8;
        g_pwt[(size_t)(n0 + n) * N_PROC + p0 + tx] = tile[tx][n];
    }
}

// ---------------------------------------------------------------------------
// Fused stage 2 (one CTA of 256 threads per token):
//   top-256 radix select on the token's acts1 row -> compact (idx,val) in smem
//   -> sparse GEMV over gathered PWT rows -> gelu -> top-128 radix select
//   -> softmax -> PV aggregation -> g_agg.
// Thread tid owns process-cols [4*tid, 4*tid+3] in the GEMV (float4, coalesced).
// ---------------------------------------------------------------------------
__global__ __launch_bounds__(256) void k_proc(const float* __restrict__ PV) {
    __shared__ int   s_cnts[32];
    __shared__ int   s_num;
    __shared__ int   s_sidx[K_IN];
    __shared__ float s_sval[K_IN];
    __shared__ int   s_idx[K_PROC];
    __shared__ float s_w[K_PROC];
    __shared__ float s_red[32];

    const int t = blockIdx.x;
    const int tid = threadIdx.x;

    // ---- stage-1 top-k on this token's acts row ----
    {
        const float* row = g_acts1 + (size_t)t * N_IN;
        unsigned keys[8]; float vals[8];
        #pragma unroll
        for (int j = 0; j < 8; j++) {
            vals[j] = row[tid + j * 256];
            keys[j] = f2key(vals[j]);
        }
        if (tid == 0) s_num = 0;    // ordered by radix's internal barrier
        const unsigned th = radix_select_kth<8>(keys, K_IN, s_cnts);
        #pragma unroll
        for (int j = 0; j < 8; j++) {
            if (keys[j] >= th) {
                const int p = atomicAdd(&s_num, 1);
                if (p < K_IN) { s_sidx[p] = tid + j * 256; s_sval[p] = vals[j]; }
            }
        }
        __syncthreads();
    }
    const int nsel = min(s_num, K_IN);   // == K_IN absent exact float ties
    __syncthreads();                     // s_num re-zeroed below

    // ---- sparse GEMV: acts2[4*tid..4*tid+3] = sum_k val_k * PWT[idx_k][...] ----
    const float4* PWT4 = (const float4*)g_pwt;    // [N_IN][N_PROC/4]
    float4 acc = make_float4(0.f, 0.f, 0.f, 0.f);
    #pragma unroll 8
    for (int k = 0; k < nsel; k++) {
        const float v = s_sval[k];
        const int   n = s_sidx[k];
        const float4 w = PWT4[(size_t)n * (N_PROC / 4) + tid];
        acc.x += v * w.x; acc.y += v * w.y; acc.z += v * w.z; acc.w += v * w.w;
    }

    float vals[4] = { gelu_exact(acc.x), gelu_exact(acc.y),
                      gelu_exact(acc.z), gelu_exact(acc.w) };
    unsigned keys[4];
    #pragma unroll
    for (int j = 0; j < 4; j++) keys[j] = f2key(vals[j]);

    // ---- top-128 + softmax + PV aggregation ----
    if (tid == 0) s_num = 0;
    const unsigned th = radix_select_kth<4>(keys, K_PROC, s_cnts);

    float lm = fmaxf(fmaxf(vals[0], vals[1]), fmaxf(vals[2], vals[3]));
    const float m = block_max(lm, s_red);   // global max is in the selected set

    #pragma unroll
    for (int j = 0; j < 4; j++) {
        if (keys[j] >= th) {
            const int p = atomicAdd(&s_num, 1);
            if (p < K_PROC) { s_idx[p] = tid * 4 + j; s_w[p] = vals[j]; }
        }
    }
    __syncthreads();
    const int num = min(s_num, K_PROC);

    float ls = 0.0f;
    for (int j = tid; j < num; j += 256) {
        const float e = expf(s_w[j] - m);
        s_w[j] = e;
        ls += e;
    }
    const float s = block_sum(ls, s_red);   // barriers publish s_w writes
    const float inv = 1.0f / s;

    // agg[d] = (1/s) * sum_k e_k * PV[idx_k][d]; d = tid (coalesced PV rows)
    float a = 0.0f;
    #pragma unroll 8
    for (int j = 0; j < num; j++)
        a += s_w[j] * PV[(size_t)s_idx[j] * D_PV + tid];
    g_agg[(size_t)t * D_PV + tid] = a * inv;
}

// ---------------------------------------------------------------------------
// Stage 3 top-k + weighted output-pattern combine. CTA(512) per token.
// ---------------------------------------------------------------------------
__global__ __launch_bounds__(512) void k_out(const float* __restrict__ OP,
                                             float* __restrict__ out) {
    __shared__ int   s_cnts[32];
    __shared__ int   s_num;
    __shared__ int   s_idx[K_OUT];
    __shared__ float s_v[K_OUT];

    const int t = blockIdx.x;
    const float* row = g_acts3 + (size_t)t * N_OUT;

    unsigned keys[4]; float vals[4];
    #pragma unroll
    for (int j = 0; j < 4; j++) {
        vals[j] = row[threadIdx.x + j * 512];
        keys[j] = f2key(vals[j]);
    }

    if (threadIdx.x == 0) s_num = 0;
    const unsigned th = radix_select_kth<4>(keys, K_OUT, s_cnts);

    #pragma unroll
    for (int j = 0; j < 4; j++) {
        if (keys[j] >= th) {
            const int p = atomicAdd(&s_num, 1);
            if (p < K_OUT) { s_idx[p] = threadIdx.x + j * 512; s_v[p] = vals[j]; }
        }
    }
    __syncthreads();
    const int num = min(s_num, K_OUT);

    const int mcol = threadIdx.x;
    float acc = 0.0f;
    #pragma unroll 8
    for (int j = 0; j < num; j++)
        acc += s_v[j] * OP[(size_t)s_idx[j] * D_MODEL + mcol];
    out[(size_t)t * D_MODEL + mcol] = acc;
}

// ---------------------------------------------------------------------------
// launch
// ---------------------------------------------------------------------------
extern "C" void kernel_launch(void* const* d_in, const int* in_sizes, int n_in,
                              void* d_out, int out_size) {
    (void)in_sizes; (void)n_in; (void)out_size;
    const float* x  = (const float*)d_in[0];  // [2,1024,512]
    const float* IP = (const float*)d_in[1];  // [2048,512]
    const float* PW = (const float*)d_in[2];  // [1024,2048]
    const float* PV = (const float*)d_in[3];  // [1024,256]
    const float* OW = (const float*)d_in[4];  // [2048,256]
    const float* OP = (const float*)d_in[5];  // [2048,512]
    float* out = (float*)d_out;               // [2,1024,512]

    k_transpose<<<dim3(N_IN / 32, N_PROC / 32), 256>>>(PW);
    k_gemm1<<<dim3(N_IN / 128, TOK / 128), 256>>>(x, IP);
    k_proc<<<TOK, 256>>>(PV);
    k_gemm3<<<dim3(N_OUT / 128, TOK / 128), 256>>>(OW);
    k_out<<<TOK, 512>>>(OP, out);
}

// round 11
// speedup vs baseline: 1.0310x; 1.0310x over previous
#include <cuda_runtime.h>
#include <math.h>

// Problem dimensions (fixed by the reference setup_inputs)
#define TOK     2048   // B*S = 2*1024
#define D_MODEL  512
#define N_IN    2048
#define N_PROC  1024
#define D_PV     256
#define N_OUT   2048
#define K_IN     256
#define K_PROC   128
#define K_OUT    256

typedef unsigned long long u64;

// Scratch (no cudaMalloc allowed): 16 + 8 + 2 + 16 = 42 MB
__device__ float g_acts1[TOK * N_IN];     // stage1 gelu acts (16 MB)
__device__ float g_pwt  [N_IN * N_PROC];  // process_input_weights^T (8 MB)
__device__ float g_agg  [TOK * D_PV];     // softmax-weighted value aggregate (2 MB)
__device__ float g_acts3[TOK * N_OUT];    // stage3 gelu acts (16 MB)

// ---------------------------------------------------------------------------
// helpers
// ---------------------------------------------------------------------------
__device__ __forceinline__ float gelu_exact(float x) {
    // jax approximate=False: 0.5*x*(1+erf(x/sqrt(2)))
    return 0.5f * x * (1.0f + erff(x * 0.70710678118654752f));
}

// packed 2xfp32 FMA (sm_100+; ptxas never emits this from C++)
__device__ __forceinline__ void ffma2(u64& d, u64 a, u64 b) {
    asm("fma.rn.f32x2 %0, %1, %2, %0;" : "+l"(d) : "l"(a), "l"(b));
}
__device__ __forceinline__ u64 pack_dup(float v) {
    u64 r; asm("mov.b64 %0, {%1, %1};" : "=l"(r) : "f"(v)); return r;
}
__device__ __forceinline__ void unpack2(u64 v, float& lo, float& hi) {
    asm("mov.b64 {%0, %1}, %2;" : "=f"(lo), "=f"(hi) : "l"(v));
}

// monotonic float -> uint mapping (no NaNs in this workload)
__device__ __forceinline__ unsigned f2key(float f) {
    unsigned u = __float_as_uint(f);
    return (u & 0x80000000u) ? ~u : (u | 0x80000000u);
}

// Exact k-th largest key across the block: 2-bit MSB radix select, 16 passes.
// Each thread holds EPT keys in registers. s_cnts: 48 ints (zeroed inside;
// 3 counters per pass, distinct slots per pass -> one barrier per pass).
// All threads of the block must participate. Returns the k-th largest key;
// selected set = (key >= returned prefix). Deterministic (integer atomics sum).
template<int EPT>
__device__ unsigned radix_select_kth(const unsigned (&keys)[EPT], int k, int* s_cnts) {
    if (threadIdx.x < 48) s_cnts[threadIdx.x] = 0;
    __syncthreads();
    unsigned prefix = 0;
    int kk = k;
    int pass = 0;
    #pragma unroll 1
    for (int b = 30; b >= 0; b -= 2, pass++) {
        // bits strictly above the pair (b+1, b); for b==30 that's none
        const unsigned mask_hi = (b == 30) ? 0u : ~((1u << (b + 2)) - 1u);
        int c1 = 0, c2 = 0, c3 = 0;
        #pragma unroll
        for (int j = 0; j < EPT; j++) {
            if ((keys[j] & mask_hi) == prefix) {
                const unsigned bucket = (keys[j] >> b) & 3u;
                c1 += (bucket == 1u);
                c2 += (bucket == 2u);
                c3 += (bucket == 3u);
            }
        }
        #pragma unroll
        for (int o = 16; o > 0; o >>= 1) {
            c1 += __shfl_xor_sync(0xffffffffu, c1, o);
            c2 += __shfl_xor_sync(0xffffffffu, c2, o);
            c3 += __shfl_xor_sync(0xffffffffu, c3, o);
        }
        if ((threadIdx.x & 31) == 0) {
            if (c1) atomicAdd(&s_cnts[pass * 3 + 0], c1);
            if (c2) atomicAdd(&s_cnts[pass * 3 + 1], c2);
            if (c3) atomicAdd(&s_cnts[pass * 3 + 2], c3);
        }
        __syncthreads();
        const int n1 = s_cnts[pass * 3 + 0];
        const int n2 = s_cnts[pass * 3 + 1];
        const int n3 = s_cnts[pass * 3 + 2];
        if (kk <= n3)                { prefix |= 3u << b; }
        else if (kk <= n3 + n2)      { prefix |= 2u << b; kk -= n3; }
        else if (kk <= n3 + n2 + n1) { prefix |= 1u << b; kk -= n3 + n2; }
        else                         {                    kk -= n3 + n2 + n1; }
        // next pass uses different counter slots -> no extra barrier
    }
    return prefix;
}

// Block-wide exclusive prefix scan of per-thread counts, in tid order.
// s_warp: >= (blockDim/32 + 1) ints. On return, *total = block sum.
// DETERMINISTIC slot assignment for compaction (replaces atomicAdd ordering,
// which varies run-to-run and broke the harness determinism check).
__device__ __forceinline__ int block_excl_scan(int cnt, int* s_warp, int* total) {
    const int lane = threadIdx.x & 31;
    const int wid  = threadIdx.x >> 5;
    const int nw   = blockDim.x >> 5;
    int incl = cnt;
    #pragma unroll
    for (int o = 1; o < 32; o <<= 1) {
        const int v = __shfl_up_sync(0xffffffffu, incl, o);
        if (lane >= o) incl += v;
    }
    if (lane == 31) s_warp[wid] = incl;
    __syncthreads();
    if (wid == 0) {
        int v = (lane < nw) ? s_warp[lane] : 0;
        #pragma unroll
        for (int o = 1; o < 32; o <<= 1) {
            const int u = __shfl_up_sync(0xffffffffu, v, o);
            if (lane >= o) v += u;
        }
        if (lane < nw) s_warp[lane] = v;   // inclusive warp-total scan
    }
    __syncthreads();
    const int warp_base = (wid == 0) ? 0 : s_warp[wid - 1];
    *total = s_warp[nw - 1];
    return warp_base + (incl - cnt);
}

__device__ __forceinline__ float block_max(float v, float* sh) {
    #pragma unroll
    for (int o = 16; o > 0; o >>= 1) v = fmaxf(v, __shfl_xor_sync(0xffffffffu, v, o));
    if ((threadIdx.x & 31) == 0) sh[threadIdx.x >> 5] = v;
    __syncthreads();
    if (threadIdx.x == 0) {
        const int nw = blockDim.x >> 5;
        float r = sh[0];
        for (int i = 1; i < nw; i++) r = fmaxf(r, sh[i]);
        sh[0] = r;
    }
    __syncthreads();
    float r = sh[0];
    __syncthreads();
    return r;
}

__device__ __forceinline__ float block_sum(float v, float* sh) {
    #pragma unroll
    for (int o = 16; o > 0; o >>= 1) v += __shfl_xor_sync(0xffffffffu, v, o);
    if ((threadIdx.x & 31) == 0) sh[threadIdx.x >> 5] = v;
    __syncthreads();
    if (threadIdx.x == 0) {
        const int nw = blockDim.x >> 5;
        float r = sh[0];
        for (int i = 1; i < nw; i++) r += sh[i];
        sh[0] = r;
    }
    __syncthreads();
    float r = sh[0];
    __syncthreads();
    return r;
}

// ---------------------------------------------------------------------------
// Tiled fp32 GEMM: C[M,N] = gelu(A[M,K] * B[N,K]^T)
// 128x128 tile, BK=8, 256 threads, 8x8 microtile, double-buffered smem,
// fma.rn.f32x2 packed inner product (bit-identical to scalar FFMA).
// __launch_bounds__(256, 2) caps regs at 128 -> 2 CTAs/SM (16 warps).
// Requires M,N % 128 == 0, K % 8 == 0 (true for all call sites).
// ---------------------------------------------------------------------------
__device__ __forceinline__ void gemm_abt_gelu_body(
        const float* __restrict__ A, const float* __restrict__ B,
        float* __restrict__ C, int N, int K) {
    __shared__ __align__(16) float As[2][8][128];
    __shared__ __align__(16) float Bs[2][8][128];

    const int tid = threadIdx.x;
    const int tx = tid & 15;         // 0..15 -> col group (8 cols each)
    const int ty = tid >> 4;         // 0..15 -> row group (8 rows each)
    const int bm = blockIdx.y * 128;
    const int bn = blockIdx.x * 128;

    const int lr = tid >> 1;         // 0..127 row within tile (load)
    const int lc = (tid & 1) << 2;   // 0 or 4 within BK (load)

    const float* Ap = A + (size_t)(bm + lr) * K + lc;
    const float* Bp = B + (size_t)(bn + lr) * K + lc;

    u64 acc2[8][4] = {};             // acc2[i][j2] = cols (2*j2, 2*j2+1) packed

    float4 a4 = *(const float4*)(Ap);
    float4 b4 = *(const float4*)(Bp);
    int buf = 0;

    for (int k0 = 0; k0 < K; k0 += 8) {
        As[buf][lc + 0][lr] = a4.x; As[buf][lc + 1][lr] = a4.y;
        As[buf][lc + 2][lr] = a4.z; As[buf][lc + 3][lr] = a4.w;
        Bs[buf][lc + 0][lr] = b4.x; Bs[buf][lc + 1][lr] = b4.y;
        Bs[buf][lc + 2][lr] = b4.z; Bs[buf][lc + 3][lr] = b4.w;
        __syncthreads();
        if (k0 + 8 < K) {                       // prefetch next k-slab
            a4 = *(const float4*)(Ap + k0 + 8);
            b4 = *(const float4*)(Bp + k0 + 8);
        }
        #pragma unroll
        for (int kk = 0; kk < 8; kk++) {
            float av[8];
            *(float4*)&av[0] = *(const float4*)&As[buf][kk][ty * 8 + 0];
            *(float4*)&av[4] = *(const float4*)&As[buf][kk][ty * 8 + 4];
            // contiguous smem fp32 pairs ARE the packed f32x2 operand
            const u64* bq = (const u64*)&Bs[buf][kk][tx * 8];
            const u64 b0 = bq[0], b1 = bq[1], b2 = bq[2], b3 = bq[3];
            #pragma unroll
            for (int i = 0; i < 8; i++) {
                const u64 ad = pack_dup(av[i]);
                ffma2(acc2[i][0], ad, b0);
                ffma2(acc2[i][1], ad, b1);
                ffma2(acc2[i][2], ad, b2);
                ffma2(acc2[i][3], ad, b3);
            }
        }
        buf ^= 1;   // safe: next write targets the other buffer; re-use of this
                    // one is fenced by the barrier in the next iteration
    }

    #pragma unroll
    for (int i = 0; i < 8; i++) {
        const int m = bm + ty * 8 + i;
        float r[8];
        #pragma unroll
        for (int j2 = 0; j2 < 4; j2++) {
            float lo, hi;
            unpack2(acc2[i][j2], lo, hi);
            r[2 * j2 + 0] = gelu_exact(lo);
            r[2 * j2 + 1] = gelu_exact(hi);
        }
        float* cp = C + (size_t)m * N + bn + tx * 8;
        *(float4*)(cp + 0) = *(const float4*)&r[0];
        *(float4*)(cp + 4) = *(const float4*)&r[4];
    }
}

__global__ __launch_bounds__(256, 2) void k_gemm1(const float* __restrict__ x,
                                                  const float* __restrict__ IP) {
    gemm_abt_gelu_body(x, IP, g_acts1, N_IN, D_MODEL);
}
__global__ __launch_bounds__(256, 2) void k_gemm3(const float* __restrict__ OW) {
    gemm_abt_gelu_body(g_agg, OW, g_acts3, N_OUT, D_PV);
}

// ---------------------------------------------------------------------------
// Transpose PW [N_PROC, N_IN] -> g_pwt [N_IN, N_PROC]
// ---------------------------------------------------------------------------
__global__ __launch_bounds__(256) void k_transpose(const float* __restrict__ PW) {
    __shared__ float tile[32][33];
    const int n0 = blockIdx.x * 32;
    const int p0 = blockIdx.y * 32;
    const int tx = threadIdx.x & 31;
    const int ty8 = threadIdx.x >> 5;       // 0..7
    #pragma unroll
    for (int i = 0; i < 4; i++) {
        const int p = ty8 + i * 8;
        tile[p][tx] = PW[(size_t)(p0 + p) * N_IN + n0 + tx];
    }
    __syncthreads();
    #pragma unroll
    for (int i = 0; i < 4; i++) {
        const int n = ty8 + i * 8;
        g_pwt[(size_t)(n0 + n) * N_PROC + p0 + tx] = tile[tx][n];
    }
}

// ---------------------------------------------------------------------------
// Fused stage 2 (one CTA of 256 threads per token):
//   top-256 radix select on the token's acts1 row -> DETERMINISTIC scan-based
//   compaction -> sparse GEMV over gathered PWT rows -> gelu -> top-128 radix
//   select -> softmax -> PV aggregation -> g_agg.
// ---------------------------------------------------------------------------
__global__ __launch_bounds__(256) void k_proc(const float* __restrict__ PV) {
    __shared__ int   s_cnts[48];
    __shared__ int   s_warp[9];
    __shared__ int   s_sidx[K_IN];
    __shared__ float s_sval[K_IN];
    __shared__ int   s_idx[K_PROC];
    __shared__ float s_w[K_PROC];
    __shared__ float s_red[32];

    const int t = blockIdx.x;
    const int tid = threadIdx.x;
    int nsel, num;

    // ---- stage-1 top-k on this token's acts row ----
    {
        const float* row = g_acts1 + (size_t)t * N_IN;
        unsigned keys[8]; float vals[8];
        #pragma unroll
        for (int j = 0; j < 8; j++) {
            vals[j] = row[tid + j * 256];
            keys[j] = f2key(vals[j]);
        }
        const unsigned th = radix_select_kth<8>(keys, K_IN, s_cnts);

        int cnt = 0;
        #pragma unroll
        for (int j = 0; j < 8; j++) cnt += (keys[j] >= th);
        int pos = block_excl_scan(cnt, s_warp, &nsel);   // deterministic slots
        #pragma unroll
        for (int j = 0; j < 8; j++) {
            if (keys[j] >= th) {
                if (pos < K_IN) { s_sidx[pos] = tid + j * 256; s_sval[pos] = vals[j]; }
                pos++;
            }
        }
        __syncthreads();
        nsel = min(nsel, K_IN);   // == K_IN absent exact float ties
    }

    // ---- sparse GEMV: acts2[4*tid..4*tid+3] = sum_k val_k * PWT[idx_k][...] ----
    // two independent accumulators: halves FMA dep-chain, deepens load batching
    const float4* PWT4 = (const float4*)g_pwt;    // [N_IN][N_PROC/4]
    float4 accA = make_float4(0.f, 0.f, 0.f, 0.f);
    float4 accB = make_float4(0.f, 0.f, 0.f, 0.f);
    int k = 0;
    #pragma unroll 4
    for (; k + 1 < nsel; k += 2) {
        const float vA = s_sval[k],     vB = s_sval[k + 1];
        const int   nA = s_sidx[k],     nB = s_sidx[k + 1];
        const float4 wA = PWT4[(size_t)nA * (N_PROC / 4) + tid];
        const float4 wB = PWT4[(size_t)nB * (N_PROC / 4) + tid];
        accA.x += vA * wA.x; accA.y += vA * wA.y; accA.z += vA * wA.z; accA.w += vA * wA.w;
        accB.x += vB * wB.x; accB.y += vB * wB.y; accB.z += vB * wB.z; accB.w += vB * wB.w;
    }
    if (k < nsel) {
        const float v = s_sval[k];
        const float4 w = PWT4[(size_t)s_sidx[k] * (N_PROC / 4) + tid];
        accA.x += v * w.x; accA.y += v * w.y; accA.z += v * w.z; accA.w += v * w.w;
    }
    const float4 acc = make_float4(accA.x + accB.x, accA.y + accB.y,
                                   accA.z + accB.z, accA.w + accB.w);

    float vals[4] = { gelu_exact(acc.x), gelu_exact(acc.y),
                      gelu_exact(acc.z), gelu_exact(acc.w) };
    unsigned keys[4];
    #pragma unroll
    for (int j = 0; j < 4; j++) keys[j] = f2key(vals[j]);

    // ---- top-128 + softmax + PV aggregation ----
    const unsigned th = radix_select_kth<4>(keys, K_PROC, s_cnts);

    float lm = fmaxf(fmaxf(vals[0], vals[1]), fmaxf(vals[2], vals[3]));
    const float m = block_max(lm, s_red);   // global max is in the selected set

    {
        int cnt = 0;
        #pragma unroll
        for (int j = 0; j < 4; j++) cnt += (keys[j] >= th);
        int pos = block_excl_scan(cnt, s_warp, &num);   // deterministic slots
        #pragma unroll
        for (int j = 0; j < 4; j++) {
            if (keys[j] >= th) {
                if (pos < K_PROC) { s_idx[pos] = tid * 4 + j; s_w[pos] = vals[j]; }
                pos++;
            }
        }
        __syncthreads();
        num = min(num, K_PROC);
    }

    float ls = 0.0f;
    for (int j = tid; j < num; j += 256) {
        const float e = expf(s_w[j] - m);
        s_w[j] = e;
        ls += e;
    }
    const float s = block_sum(ls, s_red);   // barriers publish s_w writes
    const float inv = 1.0f / s;

    // agg[d] = (1/s) * sum_k e_k * PV[idx_k][d]; d = tid (coalesced PV rows)
    float a0 = 0.0f, a1 = 0.0f;
    int j = 0;
    #pragma unroll 4
    for (; j + 1 < num; j += 2) {
        a0 += s_w[j]     * PV[(size_t)s_idx[j]     * D_PV + tid];
        a1 += s_w[j + 1] * PV[(size_t)s_idx[j + 1] * D_PV + tid];
    }
    if (j < num) a0 += s_w[j] * PV[(size_t)s_idx[j] * D_PV + tid];
    g_agg[(size_t)t * D_PV + tid] = (a0 + a1) * inv;
}

// ---------------------------------------------------------------------------
// Stage 3 top-k + weighted output-pattern combine. CTA(512) per token.
// ---------------------------------------------------------------------------
__global__ __launch_bounds__(512) void k_out(const float* __restrict__ OP,
                                             float* __restrict__ out) {
    __shared__ int   s_cnts[48];
    __shared__ int   s_warp[17];
    __shared__ int   s_idx[K_OUT];
    __shared__ float s_v[K_OUT];

    const int t = blockIdx.x;
    const float* row = g_acts3 + (size_t)t * N_OUT;

    unsigned keys[4]; float vals[4];
    #pragma unroll
    for (int j = 0; j < 4; j++) {
        vals[j] = row[threadIdx.x + j * 512];
        keys[j] = f2key(vals[j]);
    }

    const unsigned th = radix_select_kth<4>(keys, K_OUT, s_cnts);

    int num;
    {
        int cnt = 0;
        #pragma unroll
        for (int j = 0; j < 4; j++) cnt += (keys[j] >= th);
        int pos = block_excl_scan(cnt, s_warp, &num);   // deterministic slots
        #pragma unroll
        for (int j = 0; j < 4; j++) {
            if (keys[j] >= th) {
                if (pos < K_OUT) { s_idx[pos] = threadIdx.x + j * 512; s_v[pos] = vals[j]; }
                pos++;
            }
        }
        __syncthreads();
        num = min(num, K_OUT);
    }

    // out[m] = sum_k act_k * OP[idx_k][m]; dual accumulators for MLP
    const int mcol = threadIdx.x;
    float a0 = 0.0f, a1 = 0.0f;
    int j = 0;
    #pragma unroll 4
    for (; j + 1 < num; j += 2) {
        a0 += s_v[j]     * OP[(size_t)s_idx[j]     * D_MODEL + mcol];
        a1 += s_v[j + 1] * OP[(size_t)s_idx[j + 1] * D_MODEL + mcol];
    }
    if (j < num) a0 += s_v[j] * OP[(size_t)s_idx[j] * D_MODEL + mcol];
    out[(size_t)t * D_MODEL + mcol] = a0 + a1;
}

// ---------------------------------------------------------------------------
// launch
// ---------------------------------------------------------------------------
extern "C" void kernel_launch(void* const* d_in, const int* in_sizes, int n_in,
                              void* d_out, int out_size) {
    (void)in_sizes; (void)n_in; (void)out_size;
    const float* x  = (const float*)d_in[0];  // [2,1024,512]
    const float* IP = (const float*)d_in[1];  // [2048,512]
    const float* PW = (const float*)d_in[2];  // [1024,2048]
    const float* PV = (const float*)d_in[3];  // [1024,256]
    const float* OW = (const float*)d_in[4];  // [2048,256]
    const float* OP = (const float*)d_in[5];  // [2048,512]
    float* out = (float*)d_out;               // [2,1024,512]

    k_transpose<<<dim3(N_IN / 32, N_PROC / 32), 256>>>(PW);
    k_gemm1<<<dim3(N_IN / 128, TOK / 128), 256>>>(x, IP);
    k_proc<<<TOK, 256>>>(PV);
    k_gemm3<<<dim3(N_OUT / 128, TOK / 128), 256>>>(OW);
    k_out<<<TOK, 512>>>(OP, out);
}

// round 14
// speedup vs baseline: 1.0918x; 1.0589x over previous
#include <cuda_runtime.h>
#include <math.h>

// Problem dimensions (fixed by the reference setup_inputs)
#define TOK     2048   // B*S = 2*1024
#define D_MODEL  512
#define N_IN    2048
#define N_PROC  1024
#define D_PV     256
#define N_OUT   2048
#define K_IN     256
#define K_PROC   128
#define K_OUT    256

typedef unsigned long long u64;

// Scratch (no cudaMalloc allowed): 16 + 8 + 2 + 16 = 42 MB
__device__ float g_acts1[TOK * N_IN];     // stage1 gelu acts (16 MB)
__device__ float g_pwt  [N_IN * N_PROC];  // process_input_weights^T (8 MB)
__device__ float g_agg  [TOK * D_PV];     // softmax-weighted value aggregate (2 MB)
__device__ float g_acts3[TOK * N_OUT];    // stage3 gelu acts (16 MB)

// ---------------------------------------------------------------------------
// helpers
// ---------------------------------------------------------------------------
__device__ __forceinline__ float gelu_exact(float x) {
    // jax approximate=False: 0.5*x*(1+erf(x/sqrt(2)))
    return 0.5f * x * (1.0f + erff(x * 0.70710678118654752f));
}

// packed 2xfp32 FMA (sm_100+; ptxas never emits this from C++)
__device__ __forceinline__ void ffma2(u64& d, u64 a, u64 b) {
    asm("fma.rn.f32x2 %0, %1, %2, %0;" : "+l"(d) : "l"(a), "l"(b));
}
__device__ __forceinline__ u64 pack_dup(float v) {
    u64 r; asm("mov.b64 %0, {%1, %1};" : "=l"(r) : "f"(v)); return r;
}
__device__ __forceinline__ void unpack2(u64 v, float& lo, float& hi) {
    asm("mov.b64 {%0, %1}, %2;" : "=f"(lo), "=f"(hi) : "l"(v));
}

// monotonic float -> uint mapping (no NaNs in this workload)
__device__ __forceinline__ unsigned f2key(float f) {
    unsigned u = __float_as_uint(f);
    return (u & 0x80000000u) ? ~u : (u | 0x80000000u);
}

// Exact k-th largest key across the block: 2-bit MSB radix select, 16 passes.
// Each thread holds EPT keys in registers. s_cnts: 48 ints (zeroed inside;
// 3 counters per pass, distinct slots per pass -> one barrier per pass).
// All threads of the block must participate. Returns the k-th largest key;
// selected set = (key >= returned prefix). Deterministic (integer atomics sum).
template<int EPT>
__device__ unsigned radix_select_kth(const unsigned (&keys)[EPT], int k, int* s_cnts) {
    if (threadIdx.x < 48) s_cnts[threadIdx.x] = 0;
    __syncthreads();
    unsigned prefix = 0;
    int kk = k;
    int pass = 0;
    #pragma unroll 1
    for (int b = 30; b >= 0; b -= 2, pass++) {
        // bits strictly above the pair (b+1, b); for b==30 that's none
        const unsigned mask_hi = (b == 30) ? 0u : ~((1u << (b + 2)) - 1u);
        int c1 = 0, c2 = 0, c3 = 0;
        #pragma unroll
        for (int j = 0; j < EPT; j++) {
            if ((keys[j] & mask_hi) == prefix) {
                const unsigned bucket = (keys[j] >> b) & 3u;
                c1 += (bucket == 1u);
                c2 += (bucket == 2u);
                c3 += (bucket == 3u);
            }
        }
        #pragma unroll
        for (int o = 16; o > 0; o >>= 1) {
            c1 += __shfl_xor_sync(0xffffffffu, c1, o);
            c2 += __shfl_xor_sync(0xffffffffu, c2, o);
            c3 += __shfl_xor_sync(0xffffffffu, c3, o);
        }
        if ((threadIdx.x & 31) == 0) {
            if (c1) atomicAdd(&s_cnts[pass * 3 + 0], c1);
            if (c2) atomicAdd(&s_cnts[pass * 3 + 1], c2);
            if (c3) atomicAdd(&s_cnts[pass * 3 + 2], c3);
        }
        __syncthreads();
        const int n1 = s_cnts[pass * 3 + 0];
        const int n2 = s_cnts[pass * 3 + 1];
        const int n3 = s_cnts[pass * 3 + 2];
        if (kk <= n3)                { prefix |= 3u << b; }
        else if (kk <= n3 + n2)      { prefix |= 2u << b; kk -= n3; }
        else if (kk <= n3 + n2 + n1) { prefix |= 1u << b; kk -= n3 + n2; }
        else                         {                    kk -= n3 + n2 + n1; }
        // next pass uses different counter slots -> no extra barrier
    }
    return prefix;
}

// Block-wide exclusive prefix scan of per-thread counts, in tid order.
// s_warp: >= (blockDim/32 + 1) ints. On return, *total = block sum.
// DETERMINISTIC slot assignment for compaction (replaces atomicAdd ordering,
// which varies run-to-run and broke the harness determinism check).
__device__ __forceinline__ int block_excl_scan(int cnt, int* s_warp, int* total) {
    const int lane = threadIdx.x & 31;
    const int wid  = threadIdx.x >> 5;
    const int nw   = blockDim.x >> 5;
    int incl = cnt;
    #pragma unroll
    for (int o = 1; o < 32; o <<= 1) {
        const int v = __shfl_up_sync(0xffffffffu, incl, o);
        if (lane >= o) incl += v;
    }
    if (lane == 31) s_warp[wid] = incl;
    __syncthreads();
    if (wid == 0) {
        int v = (lane < nw) ? s_warp[lane] : 0;
        #pragma unroll
        for (int o = 1; o < 32; o <<= 1) {
            const int u = __shfl_up_sync(0xffffffffu, v, o);
            if (lane >= o) v += u;
        }
        if (lane < nw) s_warp[lane] = v;   // inclusive warp-total scan
    }
    __syncthreads();
    const int warp_base = (wid == 0) ? 0 : s_warp[wid - 1];
    *total = s_warp[nw - 1];
    return warp_base + (incl - cnt);
}

__device__ __forceinline__ float block_max(float v, float* sh) {
    #pragma unroll
    for (int o = 16; o > 0; o >>= 1) v = fmaxf(v, __shfl_xor_sync(0xffffffffu, v, o));
    if ((threadIdx.x & 31) == 0) sh[threadIdx.x >> 5] = v;
    __syncthreads();
    if (threadIdx.x == 0) {
        const int nw = blockDim.x >> 5;
        float r = sh[0];
        for (int i = 1; i < nw; i++) r = fmaxf(r, sh[i]);
        sh[0] = r;
    }
    __syncthreads();
    float r = sh[0];
    __syncthreads();
    return r;
}

__device__ __forceinline__ float block_sum(float v, float* sh) {
    #pragma unroll
    for (int o = 16; o > 0; o >>= 1) v += __shfl_xor_sync(0xffffffffu, v, o);
    if ((threadIdx.x & 31) == 0) sh[threadIdx.x >> 5] = v;
    __syncthreads();
    if (threadIdx.x == 0) {
        const int nw = blockDim.x >> 5;
        float r = sh[0];
        for (int i = 1; i < nw; i++) r += sh[i];
        sh[0] = r;
    }
    __syncthreads();
    float r = sh[0];
    __syncthreads();
    return r;
}

// ---------------------------------------------------------------------------
// Tiled fp32 GEMM: C[M,N] = gelu(A[M,K] * B[N,K]^T)
// 128x128 tile, BK=8, 256 threads, 8x8 microtile.
//  - B smem reads: two 4-col groups at tx*4 and 64+tx*4 -> LDS.128 at 16B lane
//    stride = conflict-free (old tx*8 mapping was 4-way conflicted).
//  - Smem rows padded 128->132 floats: row stride 528B = 16 banks mod 32, so
//    the lc=0/lc=4 fill-thread pairs land in disjoint bank halves ->
//    tile-fill STS fully conflict-free (was 2-way).
// Double-buffered; fma.rn.f32x2 packed inner product (bit-identical per
// element to scalar FFMA). __launch_bounds__(256,2) -> 2 CTAs/SM.
// Requires M,N % 128 == 0, K % 8 == 0 (true for all call sites).
// ---------------------------------------------------------------------------
#define BPAD 132
__device__ __forceinline__ void gemm_abt_gelu_body(
        const float* __restrict__ A, const float* __restrict__ B,
        float* __restrict__ C, int N, int K) {
    __shared__ __align__(16) float As[2][8][BPAD];
    __shared__ __align__(16) float Bs[2][8][BPAD];

    const int tid = threadIdx.x;
    const int tx = tid & 15;         // 0..15 -> col groups at tx*4 and 64+tx*4
    const int ty = tid >> 4;         // 0..15 -> row group (8 rows at ty*8)
    const int bm = blockIdx.y * 128;
    const int bn = blockIdx.x * 128;

    const int lr = tid >> 1;         // 0..127 row within tile (load)
    const int lc = (tid & 1) << 2;   // 0 or 4 within BK (load)

    const float* Ap = A + (size_t)(bm + lr) * K + lc;
    const float* Bp = B + (size_t)(bn + lr) * K + lc;

    // acc2[i][0..1] = cols (tx*4 .. tx*4+3); acc2[i][2..3] = cols (64+tx*4 ..)
    u64 acc2[8][4] = {};

    float4 a4 = *(const float4*)(Ap);
    float4 b4 = *(const float4*)(Bp);
    int buf = 0;

    for (int k0 = 0; k0 < K; k0 += 8) {
        As[buf][lc + 0][lr] = a4.x; As[buf][lc + 1][lr] = a4.y;
        As[buf][lc + 2][lr] = a4.z; As[buf][lc + 3][lr] = a4.w;
        Bs[buf][lc + 0][lr] = b4.x; Bs[buf][lc + 1][lr] = b4.y;
        Bs[buf][lc + 2][lr] = b4.z; Bs[buf][lc + 3][lr] = b4.w;
        __syncthreads();
        if (k0 + 8 < K) {                       // prefetch next k-slab
            a4 = *(const float4*)(Ap + k0 + 8);
            b4 = *(const float4*)(Bp + k0 + 8);
        }
        #pragma unroll
        for (int kk = 0; kk < 8; kk++) {
            float av[8];
            *(float4*)&av[0] = *(const float4*)&As[buf][kk][ty * 8 + 0];
            *(float4*)&av[4] = *(const float4*)&As[buf][kk][ty * 8 + 4];
            // two conflict-free LDS.128: 16B lane stride, contiguous 256B
            const ulonglong2 bL = *(const ulonglong2*)&Bs[buf][kk][tx * 4];
            const ulonglong2 bH = *(const ulonglong2*)&Bs[buf][kk][64 + tx * 4];
            const u64 b0 = bL.x, b1 = bL.y, b2 = bH.x, b3 = bH.y;
            #pragma unroll
            for (int i = 0; i < 8; i++) {
                const u64 ad = pack_dup(av[i]);
                ffma2(acc2[i][0], ad, b0);
                ffma2(acc2[i][1], ad, b1);
                ffma2(acc2[i][2], ad, b2);
                ffma2(acc2[i][3], ad, b3);
            }
        }
        buf ^= 1;   // safe: next write targets the other buffer; re-use of this
                    // one is fenced by the barrier in the next iteration
    }

    #pragma unroll
    for (int i = 0; i < 8; i++) {
        const int m = bm + ty * 8 + i;
        float r[8];
        #pragma unroll
        for (int j2 = 0; j2 < 4; j2++) {
            float lo, hi;
            unpack2(acc2[i][j2], lo, hi);
            r[2 * j2 + 0] = gelu_exact(lo);
            r[2 * j2 + 1] = gelu_exact(hi);
        }
        float* cpL = C + (size_t)m * N + bn + tx * 4;
        float* cpH = C + (size_t)m * N + bn + 64 + tx * 4;
        *(float4*)cpL = *(const float4*)&r[0];
        *(float4*)cpH = *(const float4*)&r[4];
    }
}

__global__ __launch_bounds__(256, 2) void k_gemm1(const float* __restrict__ x,
                                                  const float* __restrict__ IP) {
    gemm_abt_gelu_body(x, IP, g_acts1, N_IN, D_MODEL);
}
__global__ __launch_bounds__(256, 2) void k_gemm3(const float* __restrict__ OW) {
    gemm_abt_gelu_body(g_agg, OW, g_acts3, N_OUT, D_PV);
}

// ---------------------------------------------------------------------------
// Transpose PW [N_PROC, N_IN] -> g_pwt [N_IN, N_PROC]
// ---------------------------------------------------------------------------
__global__ __launch_bounds__(256) void k_transpose(const float* __restrict__ PW) {
    __shared__ float tile[32][33];
    const int n0 = blockIdx.x * 32;
    const int p0 = blockIdx.y * 32;
    const int tx = threadIdx.x & 31;
    const int ty8 = threadIdx.x >> 5;       // 0..7
    #pragma unroll
    for (int i = 0; i < 4; i++) {
        const int p = ty8 + i * 8;
        tile[p][tx] = PW[(size_t)(p0 + p) * N_IN + n0 + tx];
    }
    __syncthreads();
    #pragma unroll
    for (int i = 0; i < 4; i++) {
        const int n = ty8 + i * 8;
        g_pwt[(size_t)(n0 + n) * N_PROC + p0 + tx] = tile[tx][n];
    }
}

// ---------------------------------------------------------------------------
// Fused stage 2 (one CTA of 256 threads per token):
//   top-256 radix select on the token's acts1 row -> DETERMINISTIC scan-based
//   compaction -> sparse GEMV over gathered PWT rows -> gelu -> top-128 radix
//   select -> softmax -> PV aggregation -> g_agg.
// ---------------------------------------------------------------------------
__global__ __launch_bounds__(256) void k_proc(const float* __restrict__ PV) {
    __shared__ int   s_cnts[48];
    __shared__ int   s_warp[9];
    __shared__ int   s_sidx[K_IN];
    __shared__ float s_sval[K_IN];
    __shared__ int   s_idx[K_PROC];
    __shared__ float s_w[K_PROC];
    __shared__ float s_red[32];

    const int t = blockIdx.x;
    const int tid = threadIdx.x;
    int nsel, num;

    // ---- stage-1 top-k on this token's acts row ----
    {
        const float* row = g_acts1 + (size_t)t * N_IN;
        unsigned keys[8]; float vals[8];
        #pragma unroll
        for (int j = 0; j < 8; j++) {
            vals[j] = row[tid + j * 256];
            keys[j] = f2key(vals[j]);
        }
        const unsigned th = radix_select_kth<8>(keys, K_IN, s_cnts);

        int cnt = 0;
        #pragma unroll
        for (int j = 0; j < 8; j++) cnt += (keys[j] >= th);
        int pos = block_excl_scan(cnt, s_warp, &nsel);   // deterministic slots
        #pragma unroll
        for (int j = 0; j < 8; j++) {
            if (keys[j] >= th) {
                if (pos < K_IN) { s_sidx[pos] = tid + j * 256; s_sval[pos] = vals[j]; }
                pos++;
            }
        }
        __syncthreads();
        nsel = min(nsel, K_IN);   // == K_IN absent exact float ties
    }

    // ---- sparse GEMV: acts2[4*tid..4*tid+3] = sum_k val_k * PWT[idx_k][...] ----
    // two independent accumulators: halves FMA dep-chain, deepens load batching
    const float4* PWT4 = (const float4*)g_pwt;    // [N_IN][N_PROC/4]
    float4 accA = make_float4(0.f, 0.f, 0.f, 0.f);
    float4 accB = make_float4(0.f, 0.f, 0.f, 0.f);
    int k = 0;
    #pragma unroll 4
    for (; k + 1 < nsel; k += 2) {
        const float vA = s_sval[k],     vB = s_sval[k + 1];
        const int   nA = s_sidx[k],     nB = s_sidx[k + 1];
        const float4 wA = PWT4[(size_t)nA * (N_PROC / 4) + tid];
        const float4 wB = PWT4[(size_t)nB * (N_PROC / 4) + tid];
        accA.x += vA * wA.x; accA.y += vA * wA.y; accA.z += vA * wA.z; accA.w += vA * wA.w;
        accB.x += vB * wB.x; accB.y += vB * wB.y; accB.z += vB * wB.z; accB.w += vB * wB.w;
    }
    if (k < nsel) {
        const float v = s_sval[k];
        const float4 w = PWT4[(size_t)s_sidx[k] * (N_PROC / 4) + tid];
        accA.x += v * w.x; accA.y += v * w.y; accA.z += v * w.z; accA.w += v * w.w;
    }
    const float4 acc = make_float4(accA.x + accB.x, accA.y + accB.y,
                                   accA.z + accB.z, accA.w + accB.w);

    float vals[4] = { gelu_exact(acc.x), gelu_exact(acc.y),
                      gelu_exact(acc.z), gelu_exact(acc.w) };
    unsigned keys[4];
    #pragma unroll
    for (int j = 0; j < 4; j++) keys[j] = f2key(vals[j]);

    // ---- top-128 + softmax + PV aggregation ----
    const unsigned th = radix_select_kth<4>(keys, K_PROC, s_cnts);

    float lm = fmaxf(fmaxf(vals[0], vals[1]), fmaxf(vals[2], vals[3]));
    const float m = block_max(lm, s_red);   // global max is in the selected set

    {
        int cnt = 0;
        #pragma unroll
        for (int j = 0; j < 4; j++) cnt += (keys[j] >= th);
        int pos = block_excl_scan(cnt, s_warp, &num);   // deterministic slots
        #pragma unroll
        for (int j = 0; j < 4; j++) {
            if (keys[j] >= th) {
                if (pos < K_PROC) { s_idx[pos] = tid * 4 + j; s_w[pos] = vals[j]; }
                pos++;
            }
        }
        __syncthreads();
        num = min(num, K_PROC);
    }

    float ls = 0.0f;
    for (int j = tid; j < num; j += 256) {
        const float e = expf(s_w[j] - m);
        s_w[j] = e;
        ls += e;
    }
    const float s = block_sum(ls, s_red);   // barriers publish s_w writes
    const float inv = 1.0f / s;

    // agg[d] = (1/s) * sum_k e_k * PV[idx_k][d]; d = tid (coalesced PV rows)
    float a0 = 0.0f, a1 = 0.0f;
    int j = 0;
    #pragma unroll 4
    for (; j + 1 < num; j += 2) {
        a0 += s_w[j]     * PV[(size_t)s_idx[j]     * D_PV + tid];
        a1 += s_w[j + 1] * PV[(size_t)s_idx[j + 1] * D_PV + tid];
    }
    if (j < num) a0 += s_w[j] * PV[(size_t)s_idx[j] * D_PV + tid];
    g_agg[(size_t)t * D_PV + tid] = (a0 + a1) * inv;
}

// ---------------------------------------------------------------------------
// Stage 3 top-k + weighted output-pattern combine. CTA(512) per token.
// ---------------------------------------------------------------------------
__global__ __launch_bounds__(512) void k_out(const float* __restrict__ OP,
                                             float* __restrict__ out) {
    __shared__ int   s_cnts[48];
    __shared__ int   s_warp[17];
    __shared__ int   s_idx[K_OUT];
    __shared__ float s_v[K_OUT];

    const int t = blockIdx.x;
    const float* row = g_acts3 + (size_t)t * N_OUT;

    unsigned keys[4]; float vals[4];
    #pragma unroll
    for (int j = 0; j < 4; j++) {
        vals[j] = row[threadIdx.x + j * 512];
        keys[j] = f2key(vals[j]);
    }

    const unsigned th = radix_select_kth<4>(keys, K_OUT, s_cnts);

    int num;
    {
        int cnt = 0;
        #pragma unroll
        for (int j = 0; j < 4; j++) cnt += (keys[j] >= th);
        int pos = block_excl_scan(cnt, s_warp, &num);   // deterministic slots
        #pragma unroll
        for (int j = 0; j < 4; j++) {
            if (keys[j] >= th) {
                if (pos < K_OUT) { s_idx[pos] = threadIdx.x + j * 512; s_v[pos] = vals[j]; }
                pos++;
            }
        }
        __syncthreads();
        num = min(num, K_OUT);
    }

    // out[m] = sum_k act_k * OP[idx_k][m]; dual accumulators for MLP
    const int mcol = threadIdx.x;
    float a0 = 0.0f, a1 = 0.0f;
    int j = 0;
    #pragma unroll 4
    for (; j + 1 < num; j += 2) {
        a0 += s_v[j]     * OP[(size_t)s_idx[j]     * D_MODEL + mcol];
        a1 += s_v[j + 1] * OP[(size_t)s_idx[j + 1] * D_MODEL + mcol];
    }
    if (j < num) a0 += s_v[j] * OP[(size_t)s_idx[j] * D_MODEL + mcol];
    out[(size_t)t * D_MODEL + mcol] = a0 + a1;
}

// ---------------------------------------------------------------------------
// launch
// ---------------------------------------------------------------------------
extern "C" void kernel_launch(void* const* d_in, const int* in_sizes, int n_in,
                              void* d_out, int out_size) {
    (void)in_sizes; (void)n_in; (void)out_size;
    const float* x  = (const float*)d_in[0];  // [2,1024,512]
    const float* IP = (const float*)d_in[1];  // [2048,512]
    const float* PW = (const float*)d_in[2];  // [1024,2048]
    const float* PV = (const float*)d_in[3];  // [1024,256]
    const float* OW = (const float*)d_in[4];  // [2048,256]
    const float* OP = (const float*)d_in[5];  // [2048,512]
    float* out = (float*)d_out;               // [2,1024,512]

    k_transpose<<<dim3(N_IN / 32, N_PROC / 32), 256>>>(PW);
    k_gemm1<<<dim3(N_IN / 128, TOK / 128), 256>>>(x, IP);
    k_proc<<<TOK, 256>>>(PV);
    k_gemm3<<<dim3(N_OUT / 128, TOK / 128), 256>>>(OW);
    k_out<<<TOK, 512>>>(OP, out);
}